// round 15
// baseline (speedup 1.0000x reference)
#include <cuda_runtime.h>
#include <cuda_bf16.h>
#include <cstdint>
#include <cstddef>

#define B_  8
#define N_  2048
#define LDF 512

// ---------------- scratch (device globals: allocation-free) ----------------
__device__ __align__(16) float g_X0[B_ * N_ * 3];
__device__ __align__(16) float g_F [B_ * N_ * LDF];      // concat features [b][n][512]
__device__ __align__(16) float g_Z [B_ * N_ * LDF];      // z = W' x, rows [m][2O]
__device__ __align__(16) float g_SQ[B_ * N_];
__device__ __align__(16) int   g_ID[B_ * N_ * 4];
__device__ __align__(16) int   g_C8[B_ * N_ * 8];        // knn top-8 candidates
__device__ __align__(16) float g_WPf[512 * 128];         // packed W' fp32 (L1 only)
__device__ __align__(16) __nv_bfloat16 g_Xb[B_ * N_ * 1536]; // compact [h|l] of F (final)
__device__ __align__(16) __nv_bfloat16 g_Xc[B_ * N_ * 256];  // compact [h|l] (knn + z acts)
__device__ __align__(16) __nv_bfloat16 g_Wb[512 * 1536];     // compact [h|l] weights

__device__ __forceinline__ uint32_t s2u(const void* p) {
    uint32_t a;
    asm("{ .reg .u64 t; cvta.to.shared.u64 t, %1; cvt.u32.u64 %0, t; }" : "=r"(a) : "l"(p));
    return a;
}
// ---- cp.async helpers ----
__device__ __forceinline__ void cp16(uint32_t dst, const void* src) {
    asm volatile("cp.async.cg.shared.global [%0], [%1], 16;" :: "r"(dst), "l"(src));
}
#define CP_COMMIT() asm volatile("cp.async.commit_group;" ::: "memory")
#define CP_WAIT1()  asm volatile("cp.async.wait_group 1;" ::: "memory")

// ---------------- transpose x (B,3,N) -> X0 [b][n][3] ----------------
__global__ void tr_x0_k(const float* __restrict__ x, float* __restrict__ X0)
{
    int t = blockIdx.x * blockDim.x + threadIdx.x;
    const int tot = B_ * 3 * N_;
    if (t >= tot) return;
    int b = t / (3 * N_);
    int r = t % (3 * N_);
    int c = r / N_;
    int n = r % N_;
    X0[((size_t)b * N_ + n) * 3 + c] = x[t];
}

// ---------------- squared norms (L1 only) ----------------
__global__ void sqnorm_k(const float* __restrict__ X, int ldx, int C,
                         float* __restrict__ sq)
{
    int w    = (blockIdx.x * blockDim.x + threadIdx.x) >> 5;
    int lane = threadIdx.x & 31;
    if (w >= B_ * N_) return;
    const float* r = X + (size_t)w * ldx;
    float s = 0.f;
    for (int c = lane; c < C; c += 32) { float v = r[c]; s += v * v; }
    #pragma unroll
    for (int o = 16; o; o >>= 1) s += __shfl_xor_sync(0xffffffffu, s, o);
    if (lane == 0) sq[w] = s;
}

// ------ fused: squared norm + compact [h|l] split, one pass over X --------
__global__ void prep_k(const float* __restrict__ X, int ldx, int C,
                       float* __restrict__ sq, __nv_bfloat16* __restrict__ dst)
{
    int w    = (blockIdx.x * blockDim.x + threadIdx.x) >> 5;
    int lane = threadIdx.x & 31;
    if (w >= B_ * N_) return;
    const float* r = X + (size_t)w * ldx;
    __nv_bfloat16* d = dst + (size_t)w * (2 * C);
    float s = 0.f;
    for (int c = lane; c < C; c += 32) {
        float v = r[c];
        s += v * v;
        float h = __bfloat162float(__float2bfloat16(v));
        d[c]     = __float2bfloat16(h);
        d[C + c] = __float2bfloat16(v - h);
    }
    #pragma unroll
    for (int o = 16; o; o >>= 1) s += __shfl_xor_sync(0xffffffffu, s, o);
    if (lane == 0) sq[w] = s;
}

// ------ fused: pack W (O x 2C) -> W' (2O x C) AND compact [h|l] split -----
__global__ void packsplit_k(const float* __restrict__ W, int O, int C,
                            __nv_bfloat16* __restrict__ dst)
{
    int t = blockIdx.x * blockDim.x + threadIdx.x;
    int Kc = 2 * C;
    int tot = 2 * O * Kc;
    if (t >= tot) return;
    int col = t % Kc;
    int r   = t / Kc;
    int c   = (col < C) ? col : col - C;
    float x = (r < O) ? W[r * (2*C) + c] : W[(r - O) * (2*C) + C + c];
    float h = __bfloat162float(__float2bfloat16(x));
    float v = (col < C) ? h : (x - h);
    dst[t] = __float2bfloat16(v);
}

// ---------------- top-D insertion (value desc, tie: lower index) ----------
template<int D>
__device__ __forceinline__ void topD_insert(float d, int id, float (&v)[D], int (&ix)[D])
{
    if (d > v[D-1] || (d == v[D-1] && id < ix[D-1])) {
        v[D-1] = d; ix[D-1] = id;
        #pragma unroll
        for (int s = D-1; s > 0; s--) {
            if (v[s] > v[s-1] || (v[s] == v[s-1] && ix[s] < ix[s-1])) {
                float tv = v[s]; v[s] = v[s-1]; v[s-1] = tv;
                int   ti = ix[s]; ix[s] = ix[s-1]; ix[s-1] = ti;
            } else break;
        }
    }
}
__device__ __forceinline__ void top4_insert(float d, int id, float (&v)[4], int (&ix)[4])
{ topD_insert<4>(d, id, v, ix); }

// ---------------- fused KNN for C=3 (fp32-exact) --------------------------
__global__ __launch_bounds__(256) void knn3_kernel(const float* __restrict__ X,
                                                   const float* __restrict__ sq,
                                                   int* __restrict__ out_idx)
{
    constexpr int C = 3, QROW = 68;
    __shared__ __align__(16) float pool[64 * 64 * 2];
    float* Qs = pool;
    float* Ks = pool + C * QROW;

    const int b  = blockIdx.y;
    const int q0 = blockIdx.x * 64;
    const int t  = threadIdx.x;
    const int tx = t & 15, ty = t >> 4;
    const size_t rb = (size_t)b * N_;

    for (int f = t; f < 64 * C; f += 256) {
        int c = f % C, m = f / C;
        Qs[c*QROW + m] = X[(rb + q0 + m) * 3 + c];
    }

    float sqq[4];
    #pragma unroll
    for (int i = 0; i < 4; i++) sqq[i] = sq[rb + q0 + ty*4 + i];

    float bv[4][4]; int bix[4][4];
    #pragma unroll
    for (int i = 0; i < 4; i++)
        #pragma unroll
        for (int j = 0; j < 4; j++) { bv[i][j] = -3.4e38f; bix[i][j] = 0x7fffffff; }

    for (int kb = 0; kb < N_; kb += 64) {
        float acc[4][4];
        #pragma unroll
        for (int i = 0; i < 4; i++)
            #pragma unroll
            for (int j = 0; j < 4; j++) acc[i][j] = 0.f;

        __syncthreads();
        for (int f = t; f < 64 * C; f += 256) {
            int c = f % C, m = f / C;
            Ks[c*QROW + m] = X[(rb + kb + m) * 3 + c];
        }
        __syncthreads();
        #pragma unroll
        for (int c = 0; c < C; c++) {
            float4 q4 = *(const float4*)&Qs[c*QROW + ty*4];
            float4 k4 = *(const float4*)&Ks[c*QROW + tx*4];
            float qa[4] = {q4.x, q4.y, q4.z, q4.w};
            float ka[4] = {k4.x, k4.y, k4.z, k4.w};
            #pragma unroll
            for (int i = 0; i < 4; i++)
                #pragma unroll
                for (int j = 0; j < 4; j++)
                    acc[i][j] += qa[i] * ka[j];
        }

        float sqk[4];
        #pragma unroll
        for (int j = 0; j < 4; j++) sqk[j] = sq[rb + kb + tx*4 + j];

        #pragma unroll
        for (int i = 0; i < 4; i++)
            #pragma unroll
            for (int j = 0; j < 4; j++) {
                float d = 2.0f * acc[i][j] - sqq[i] - sqk[j];
                top4_insert(d, kb + tx*4 + j, bv[i], bix[i]);
            }
    }

    __syncthreads();
    float* cv = pool;
    int*   ci = (int*)(pool + 64 * 64);
    #pragma unroll
    for (int qi = 0; qi < 4; qi++) {
        int base = (ty*4 + qi) * 64 + tx * 4;
        #pragma unroll
        for (int r = 0; r < 4; r++) { cv[base + r] = bv[qi][r]; ci[base + r] = bix[qi][r]; }
    }
    __syncthreads();
    if (t < 64) {
        float v4[4]; int i4[4];
        #pragma unroll
        for (int r = 0; r < 4; r++) { v4[r] = -3.4e38f; i4[r] = 0x7fffffff; }
        for (int j = 0; j < 64; j++)
            top4_insert(cv[t*64 + j], ci[t*64 + j], v4, i4);
        int* op = out_idx + (rb + q0 + t) * 4;
        op[0] = i4[0]; op[1] = i4[1]; op[2] = i4[2]; op[3] = i4[3];
    }
}

// ---------------- HMMA helpers ----------------
__device__ __forceinline__ void ldmx4(uint32_t (&r)[4], uint32_t addr)
{
    asm volatile("ldmatrix.sync.aligned.m8n8.x4.shared.b16 {%0,%1,%2,%3}, [%4];"
                 : "=r"(r[0]), "=r"(r[1]), "=r"(r[2]), "=r"(r[3]) : "r"(addr));
}
__device__ __forceinline__ void mma16816(float (&d)[4], const uint32_t (&a)[4],
                                         uint32_t b0, uint32_t b1)
{
    asm volatile(
        "mma.sync.aligned.m16n8k16.row.col.f32.bf16.bf16.f32 "
        "{%0,%1,%2,%3}, {%4,%5,%6,%7}, {%8,%9}, {%0,%1,%2,%3};"
        : "+f"(d[0]), "+f"(d[1]), "+f"(d[2]), "+f"(d[3])
        : "r"(a[0]), "r"(a[1]), "r"(a[2]), "r"(a[3]), "r"(b0), "r"(b1));
}

// ------- compact split: fp32 -> [h | l] bf16 limbs (2C cols) --------------
__global__ void split_hl(const float* __restrict__ src, int lds, int C, int R,
                         __nv_bfloat16* __restrict__ dst)
{
    int t = blockIdx.x * blockDim.x + threadIdx.x;
    int Kc = 2 * C;
    int tot = R * Kc;
    if (t >= tot) return;
    int col = t % Kc;
    int r   = t / Kc;
    int c   = (col < C) ? col : col - C;
    float x = src[(size_t)r * lds + c];
    float h = __bfloat162float(__float2bfloat16(x));
    float v = (col < C) ? h : (x - h);
    dst[t] = __float2bfloat16(v);
}

// ===== HMMA KNN on compact [h|l]: 3-term expansion via chunk addressing ===
template<int C>
__global__ __launch_bounds__(256) void knn_mma2(const __nv_bfloat16* __restrict__ XC,
                                                const float* __restrict__ sq,
                                                int* __restrict__ cand)
{
    constexpr int Kc    = 2 * C;
    constexpr int AKROW = Kc + 8;
    constexpr int BSTG  = 128 * AKROW;
    constexpr int NEXP  = (3 * C) / 64;
    constexpr int NBUF  = (C == 64) ? 3 : 2;
    constexpr int NT    = N_ / 128;
    constexpr int NCP   = Kc / 16;
    extern __shared__ __align__(16) float knnpool[];
    __nv_bfloat16* As = (__nv_bfloat16*)knnpool;
    __nv_bfloat16* Bs = As + BSTG;

    int AOFF[NEXP], BOFF[NEXP];
    if constexpr (C == 64) {
        AOFF[0] = 0;  AOFF[1] = 0;   AOFF[2] = 64;
        BOFF[0] = 0;  BOFF[1] = 64;  BOFF[2] = 0;
    } else {
        AOFF[0] = 0;   AOFF[1] = 64;  AOFF[2] = 0;   AOFF[3] = 64;  AOFF[4] = 128; AOFF[5] = 192;
        BOFF[0] = 0;   BOFF[1] = 64;  BOFF[2] = 128; BOFF[3] = 192; BOFF[4] = 0;   BOFF[5] = 64;
    }

    const int b  = blockIdx.y;
    const int q0 = blockIdx.x * 128;
    const size_t rb = (size_t)b * N_;
    const int t = threadIdx.x, wid = t >> 5, lane = t & 31;
    const int wm = wid & 1, wn = wid >> 1;
    const int gid = lane >> 2, tig = lane & 3;
    const uint32_t uA = s2u(As), uB = s2u(Bs);

    for (int idx = t; idx < 128 * (Kc / 8); idx += 256) {
        int r = idx / (Kc / 8), c8 = idx % (Kc / 8);
        uint4 v = *(const uint4*)(XC + (rb + q0 + r) * (size_t)Kc + c8 * 8);
        *(uint4*)(As + r * AKROW + c8 * 8) = v;
    }
    __syncthreads();

    const int a_r  = wm * 64 + (lane & 15);
    const int a_c8 = (lane >> 4) * 8;
    const int b_rl = wn * 32 + ((lane >> 4) << 3) + (lane & 7);
    const int b_c8 = ((lane >> 3) & 1) * 8;

    float sqq8[8];
    #pragma unroll
    for (int i = 0; i < 8; i++) {
        int mt = i >> 1, h = i & 1;
        sqq8[i] = sq[rb + q0 + wm * 64 + mt * 16 + h * 8 + gid];
    }

    float bv[8][4]; int bix[8][4];
    #pragma unroll
    for (int i = 0; i < 8; i++)
        #pragma unroll
        for (int j = 0; j < 4; j++) { bv[i][j] = -3.4e38f; bix[i][j] = 0x7fffffff; }

    auto kissue = [&](int kt2) {
        if (kt2 < NT) {
            int s = kt2 % NBUF;
            const __nv_bfloat16* p = XC + (rb + kt2 * 128) * (size_t)Kc;
            uint32_t db = uB + 2u * (s * BSTG);
            #pragma unroll
            for (int q = 0; q < NCP; q++) {
                int idx = t + q * 256;
                int r = idx / (Kc / 8), c8 = idx % (Kc / 8);
                cp16(db + 2u * (r * AKROW + c8 * 8),
                     p + (size_t)r * Kc + c8 * 8);
            }
        }
        CP_COMMIT();
    };

    kissue(0); kissue(1);
    for (int kt = 0; kt < NT; kt++) {
        CP_WAIT1();
        __syncthreads();
        const uint32_t uBs = uB + 2u * ((kt % NBUF) * BSTG);

        float acc[4][4][4];
        #pragma unroll
        for (int mt = 0; mt < 4; mt++)
            #pragma unroll
            for (int nt = 0; nt < 4; nt++)
                #pragma unroll
                for (int e = 0; e < 4; e++) acc[mt][nt][e] = 0.f;

        #pragma unroll
        for (int i = 0; i < NEXP; i++) {
            #pragma unroll
            for (int ks = 0; ks < 64; ks += 16) {
                uint32_t af[4][4], bf[2][4];
                #pragma unroll
                for (int mt = 0; mt < 4; mt++)
                    ldmx4(af[mt], uA + 2u * ((a_r + mt * 16) * AKROW + AOFF[i] + ks + a_c8));
                #pragma unroll
                for (int n2 = 0; n2 < 2; n2++)
                    ldmx4(bf[n2], uBs + 2u * ((b_rl + n2 * 16) * AKROW + BOFF[i] + ks + b_c8));
                #pragma unroll
                for (int mt = 0; mt < 4; mt++)
                    #pragma unroll
                    for (int nt = 0; nt < 4; nt++)
                        mma16816(acc[mt][nt], af[mt],
                                 bf[nt >> 1][(nt & 1) * 2], bf[nt >> 1][(nt & 1) * 2 + 1]);
            }
        }
        if constexpr (NBUF == 2) __syncthreads();
        kissue(kt + 2);

        #pragma unroll
        for (int nt = 0; nt < 4; nt++) {
            int c0 = kt * 128 + wn * 32 + nt * 8 + tig * 2;
            float sk0 = sq[rb + c0], sk1 = sq[rb + c0 + 1];
            #pragma unroll
            for (int mt = 0; mt < 4; mt++)
                #pragma unroll
                for (int e = 0; e < 4; e++) {
                    int i8 = mt * 2 + (e >> 1);
                    float d = 2.0f * acc[mt][nt][e] - sqq8[i8] - ((e & 1) ? sk1 : sk0);
                    top4_insert(d, c0 + (e & 1), bv[i8], bix[i8]);
                }
        }
    }

    __syncthreads();
    float* cv = knnpool;
    int*   ci = (int*)(knnpool + 128 * 64);
    #pragma unroll
    for (int i = 0; i < 8; i++) {
        int mt = i >> 1, h = i & 1;
        int rowL = wm * 64 + mt * 16 + h * 8 + gid;
        int slot = wn * 16 + tig * 4;
        #pragma unroll
        for (int j = 0; j < 4; j++) {
            cv[rowL * 64 + slot + j] = bv[i][j];
            ci[rowL * 64 + slot + j] = bix[i][j];
        }
    }
    __syncthreads();
    if (t < 128) {
        float v8[8]; int i8[8];
        #pragma unroll
        for (int r = 0; r < 8; r++) { v8[r] = -3.4e38f; i8[r] = 0x7fffffff; }
        for (int j = 0; j < 64; j++)
            topD_insert<8>(cv[t * 64 + j], ci[t * 64 + j], v8, i8);
        int* op = cand + (rb + q0 + t) * 8;
        #pragma unroll
        for (int r = 0; r < 8; r++) op[r] = i8[r];
    }
}

static inline int knn2_smem(int C) {
    int Kc = 2 * C, row = Kc + 8;
    int nbuf = (C == 64) ? 3 : 2;
    int tot = (1 + nbuf) * 128 * row * 2;
    int mg = 128 * 64 * 8;
    return tot > mg ? tot : mg;
}

// ==== fused: exact fp32 fixup (top8 cand -> top4) + edge epilogue =========
__global__ void fix_epi_k(const float* __restrict__ X, int ldx, int C,
                          const float* __restrict__ sq,
                          const int* __restrict__ cand,
                          const float* __restrict__ Z,
                          float* __restrict__ Fo, int O)
{
    __shared__ int sid[4];
    const int b = blockIdx.y, n = blockIdx.x;
    const size_t rb = (size_t)b * N_;
    const size_t w = rb + n;
    const int t = threadIdx.x, lane = t & 31;

    if (t < 32) {
        int id = 0; float d = -3.4e38f;
        if (lane < 8) {
            id = cand[w * 8 + lane];
            const float* qp = X + w * (size_t)ldx;
            const float* kp = X + (rb + id) * (size_t)ldx;
            float dot = 0.f;
            for (int c = 0; c < C; c += 4) {
                float4 a = *(const float4*)(qp + c);
                float4 b2 = *(const float4*)(kp + c);
                dot += a.x * b2.x + a.y * b2.y + a.z * b2.z + a.w * b2.w;
            }
            d = 2.0f * dot - sq[w] - sq[rb + id];
        }
        float v4[4]; int i4[4];
        #pragma unroll
        for (int r = 0; r < 4; r++) { v4[r] = -3.4e38f; i4[r] = 0x7fffffff; }
        #pragma unroll
        for (int j = 0; j < 8; j++) {
            float dj = __shfl_sync(0xffffffffu, d, j);
            int   ij = __shfl_sync(0xffffffffu, id, j);
            top4_insert(dj, ij, v4, i4);
        }
        if (lane == 0) { sid[0] = i4[0]; sid[1] = i4[1]; sid[2] = i4[2]; sid[3] = i4[3]; }
    }
    __syncthreads();
    int4 id = *(int4*)sid;
    const size_t wz = (size_t)(2 * O);
    const float* zb = Z + rb * wz;
    const float* z0 = zb + (size_t)id.x * wz;
    const float* z1 = zb + (size_t)id.y * wz;
    const float* z2 = zb + (size_t)id.z * wz;
    const float* z3 = zb + (size_t)id.w * wz;
    const float* zc = zb + (size_t)n * wz + O;
    float* fo = Fo + w * LDF;
    for (int o = t; o < O; o += blockDim.x) {
        float m = fmaxf(fmaxf(z0[o], z1[o]), fmaxf(z2[o], z3[o]));
        fo[o] = fmaxf(m + zc[o], 0.f);
    }
}

// ---------------- pack W (O x 2C) -> W' (2O x C) fp32 (L1 only) -----------
__global__ void packw_k(const float* __restrict__ W, float* __restrict__ Wp, int O, int Cc)
{
    int t = blockIdx.x * blockDim.x + threadIdx.x;
    int tot = 2 * O * Cc;
    if (t >= tot) return;
    int r = t / Cc, c = t % Cc;
    Wp[t] = (r < O) ? W[r * (2*Cc) + c] : W[(r - O) * (2*Cc) + Cc + c];
}

// ---------------- SIMT NT SGEMM (L1 only, K=3) ----------------------------
__device__ __forceinline__ void g2s_tile(float* S, const float* M, int ld,
                                         int r0, int k0, int K, int cq, int li)
{
    const float* rp = M + (size_t)(r0 + li) * ld;
    int c = k0 + cq * 4;
    float x, y, z, w;
    if (c + 3 < K && (((uintptr_t)(rp + c) & 15u) == 0)) {
        float4 v = *(const float4*)(rp + c);
        x = v.x; y = v.y; z = v.z; w = v.w;
    } else {
        x = (c + 0 < K) ? rp[c + 0] : 0.f;
        y = (c + 1 < K) ? rp[c + 1] : 0.f;
        z = (c + 2 < K) ? rp[c + 2] : 0.f;
        w = (c + 3 < K) ? rp[c + 3] : 0.f;
    }
    S[(cq*4+0)*68 + li] = x;
    S[(cq*4+1)*68 + li] = y;
    S[(cq*4+2)*68 + li] = z;
    S[(cq*4+3)*68 + li] = w;
}

__global__ __launch_bounds__(256) void gemm_nt(int K,
    const float* __restrict__ A,  int lda, size_t sA,
    const float* __restrict__ Bm, int ldb, size_t sB,
    float* __restrict__ Cm,       int ldc, size_t sC)
{
    __shared__ __align__(16) float As[16 * 68];
    __shared__ __align__(16) float Bs[16 * 68];
    const int bz = blockIdx.z;
    A  += (size_t)bz * sA;
    Bm += (size_t)bz * sB;
    Cm += (size_t)bz * sC;
    const int i0 = blockIdx.y * 64, j0 = blockIdx.x * 64;
    const int t  = threadIdx.x;
    const int tx = t & 15, ty = t >> 4;
    const int cq = t & 3,  li = t >> 2;

    float acc[4][4];
    #pragma unroll
    for (int i = 0; i < 4; i++)
        #pragma unroll
        for (int j = 0; j < 4; j++) acc[i][j] = 0.f;

    for (int k0 = 0; k0 < K; k0 += 16) {
        g2s_tile(As, A,  lda, i0, k0, K, cq, li);
        g2s_tile(Bs, Bm, ldb, j0, k0, K, cq, li);
        __syncthreads();
        #pragma unroll
        for (int c = 0; c < 16; c++) {
            float4 a4 = *(const float4*)&As[c*68 + ty*4];
            float4 b4 = *(const float4*)&Bs[c*68 + tx*4];
            float aa[4] = {a4.x, a4.y, a4.z, a4.w};
            float bb[4] = {b4.x, b4.y, b4.z, b4.w};
            #pragma unroll
            for (int i = 0; i < 4; i++)
                #pragma unroll
                for (int j = 0; j < 4; j++)
                    acc[i][j] += aa[i] * bb[j];
        }
        __syncthreads();
    }
    #pragma unroll
    for (int r = 0; r < 4; r++) {
        float4 v = make_float4(acc[r][0], acc[r][1], acc[r][2], acc[r][3]);
        *(float4*)&Cm[(size_t)(i0 + ty*4 + r) * ldc + j0 + tx*4] = v;
    }
}

// ====== HMMA bf16 NT-GEMM on COMPACT [h|l], 2-stage ring, 2 CTAs/SM =======
#define KC   64
#define KPAD 8
#define AROW (KC + KPAD)
#define GSTG (128 * AROW)
#define GSMEM (2 * GSTG * 2 * 2)          // 2 stages x (A+B) x bf16

__global__ __launch_bounds__(256, 2) void gemm_mmac(int tpt, int Cc,
    unsigned selA, unsigned selB,
    const __nv_bfloat16* __restrict__ A, int lda, size_t sA,
    const __nv_bfloat16* __restrict__ B, int ldb, size_t sB,
    float* __restrict__ D, int ldd, size_t sD)
{
    extern __shared__ __align__(16) __nv_bfloat16 gsm[];
    __nv_bfloat16* As = gsm;
    __nv_bfloat16* Bs = gsm + 2 * GSTG;
    const int bz = blockIdx.z;
    A += (size_t)bz * sA;
    B += (size_t)bz * sB;
    D += (size_t)bz * sD;
    const int i0 = blockIdx.y * 128;
    const int j0 = blockIdx.x * 128;
    const int t = threadIdx.x, wid = t >> 5, lane = t & 31;
    const int wm = wid & 1, wn = wid >> 1;
    const int gid = lane >> 2, tig = lane & 3;

    const uint32_t uA = s2u(As), uB = s2u(Bs);

    const int a_r  = wm * 64 + (lane & 15);
    const int a_c8 = (lane >> 4) * 8;
    const int b_r  = wn * 32 + ((lane >> 4) << 3) + (lane & 7);
    const int b_c8 = ((lane >> 3) & 1) * 8;

    float acc[4][4][4];
    #pragma unroll
    for (int mt = 0; mt < 4; mt++)
        #pragma unroll
        for (int nt = 0; nt < 4; nt++)
            #pragma unroll
            for (int e = 0; e < 4; e++) acc[mt][nt][e] = 0.f;

    const int nk = 3 * tpt;

    auto issue = [&](int k2) {
        if (k2 < nk) {
            int s = k2 & 1;
            int tb = k2 / tpt, ic = k2 % tpt;
            int offA = ic * 64 + (int)((selA >> tb) & 1u) * Cc;
            int offB = ic * 64 + (int)((selB >> tb) & 1u) * Cc;
            const __nv_bfloat16* Ag = A + (size_t)i0 * lda + offA;
            const __nv_bfloat16* Bg = B + (size_t)j0 * ldb + offB;
            uint32_t da = uA + 2u * (s * GSTG);
            uint32_t db = uB + 2u * (s * GSTG);
            #pragma unroll
            for (int q = 0; q < 4; q++) {
                int idx = t + q * 256;
                int r = idx >> 3, c8 = idx & 7;
                cp16(da + 2u * (r * AROW + c8 * 8), Ag + (size_t)r * lda + c8 * 8);
                cp16(db + 2u * (r * AROW + c8 * 8), Bg + (size_t)r * ldb + c8 * 8);
            }
        }
        CP_COMMIT();
    };

    issue(0); issue(1);
    for (int k = 0; k < nk; k++) {
        CP_WAIT1();
        __syncthreads();
        const int s = k & 1;
        const uint32_t uAs = uA + 2u * (s * GSTG);
        const uint32_t uBs = uB + 2u * (s * GSTG);
        #pragma unroll
        for (int ks = 0; ks < KC; ks += 16) {
            uint32_t af[4][4], bf[2][4];
            #pragma unroll
            for (int mt = 0; mt < 4; mt++)
                ldmx4(af[mt], uAs + 2u * ((a_r + mt * 16) * AROW + ks + a_c8));
            #pragma unroll
            for (int n2 = 0; n2 < 2; n2++)
                ldmx4(bf[n2], uBs + 2u * ((b_r + n2 * 16) * AROW + ks + b_c8));
            #pragma unroll
            for (int mt = 0; mt < 4; mt++)
                #pragma unroll
                for (int nt = 0; nt < 4; nt++)
                    mma16816(acc[mt][nt], af[mt],
                             bf[nt >> 1][(nt & 1) * 2], bf[nt >> 1][(nt & 1) * 2 + 1]);
        }
        __syncthreads();            // all warps done reading stage s
        issue(k + 2);               // safe to overwrite stage s
    }

    #pragma unroll
    for (int mt = 0; mt < 4; mt++) {
        int r = i0 + wm * 64 + mt * 16 + gid;
        #pragma unroll
        for (int nt = 0; nt < 4; nt++) {
            int c = j0 + wn * 32 + nt * 8 + tig * 2;
            *(float2*)&D[(size_t)r * ldd + c]       = make_float2(acc[mt][nt][0], acc[mt][nt][1]);
            *(float2*)&D[(size_t)(r + 8) * ldd + c] = make_float2(acc[mt][nt][2], acc[mt][nt][3]);
        }
    }
}

// ---------------- gather + relu + max-over-k epilogue (L1) ----------------
__global__ void edge_epi_k(const float* __restrict__ Z, const int* __restrict__ idx,
                           float* __restrict__ Fo, int O)
{
    const int b = blockIdx.y, n = blockIdx.x;
    const size_t rb = (size_t)b * N_;
    int4 id = *(const int4*)(idx + (rb + n) * 4);
    const size_t w = (size_t)(2 * O);
    const float* zb = Z + rb * w;
    const float* z0 = zb + (size_t)id.x * w;
    const float* z1 = zb + (size_t)id.y * w;
    const float* z2 = zb + (size_t)id.z * w;
    const float* z3 = zb + (size_t)id.w * w;
    const float* zc = zb + (size_t)n * w + O;
    float* fo = Fo + (rb + n) * LDF;
    for (int o = threadIdx.x; o < O; o += blockDim.x) {
        float m = fmaxf(fmaxf(z0[o], z1[o]), fmaxf(z2[o], z3[o]));
        fo[o] = fmaxf(m + zc[o], 0.f);
    }
}

// ---------------- orchestration ----------------
extern "C" void kernel_launch(void* const* d_in, const int* in_sizes, int n_in,
                              void* d_out, int out_size)
{
    const float* x  = (const float*)d_in[0];
    const float* W1 = (const float*)d_in[1];
    const float* W2 = (const float*)d_in[2];
    const float* W3 = (const float*)d_in[3];
    const float* W4 = (const float*)d_in[4];
    const float* W5 = (const float*)d_in[5];
    float* out = (float*)d_out;

    void* p;
    cudaGetSymbolAddress(&p, g_X0);  float* X0 = (float*)p;
    cudaGetSymbolAddress(&p, g_F );  float* F  = (float*)p;
    cudaGetSymbolAddress(&p, g_Z );  float* Z  = (float*)p;
    cudaGetSymbolAddress(&p, g_SQ);  float* SQ = (float*)p;
    cudaGetSymbolAddress(&p, g_ID);  int*   ID = (int*)p;
    cudaGetSymbolAddress(&p, g_C8);  int*   C8 = (int*)p;
    cudaGetSymbolAddress(&p, g_WPf); float* WPf = (float*)p;
    cudaGetSymbolAddress(&p, g_Xb);  __nv_bfloat16* Xb = (__nv_bfloat16*)p;
    cudaGetSymbolAddress(&p, g_Xc);  __nv_bfloat16* Xc = (__nv_bfloat16*)p;
    cudaGetSymbolAddress(&p, g_Wb);  __nv_bfloat16* Wb = (__nv_bfloat16*)p;

    cudaFuncSetAttribute(knn_mma2<64>,
        cudaFuncAttributeMaxDynamicSharedMemorySize, knn2_smem(64));
    cudaFuncSetAttribute(knn_mma2<128>,
        cudaFuncAttributeMaxDynamicSharedMemorySize, knn2_smem(128));
    cudaFuncSetAttribute(gemm_mmac,
        cudaFuncAttributeMaxDynamicSharedMemorySize, GSMEM);

    // sel bits per term (0=h,1=l): activations {h,h,l} -> 0b100,
    //                              weights     {h,l,h} -> 0b010
    const unsigned SEL_ACT = 0b100u;
    const unsigned SEL_W   = 0b010u;

    tr_x0_k<<<(B_*3*N_ + 255)/256, 256>>>(x, X0);

    // ---- layer 1: fp32 knn (C=3) + SIMT z-GEMM + plain epilogue
    {
        sqnorm_k<<<(B_*N_*32)/256, 256>>>(X0, 3, 3, SQ);
        knn3_kernel<<<dim3(N_/64, B_), 256>>>(X0, SQ, ID);
        packw_k<<<(2*64*3 + 255)/256, 256>>>(W1, WPf, 64, 3);
        dim3 gg(128/64, (B_*N_)/64, 1);
        gemm_nt<<<gg, 256>>>(3, X0, 3, (size_t)0, WPf, 3, (size_t)0,
                             Z, 128, (size_t)0);
        edge_epi_k<<<dim3(N_, B_), 64>>>(Z, ID, F + 0, 64);
    }

    // ---- layers 2-4: HMMA knn + compact HMMA z-GEMM (reuses Xc) ----------
    auto layer_tc = [&](const float* Xin, int C, int O, const float* W, float* Fout) {
        prep_k<<<(B_*N_*32)/256, 256>>>(Xin, LDF, C, SQ, Xc);
        dim3 kg(N_/128, B_);
        if (C == 64)
            knn_mma2<64> <<<kg, 256, knn2_smem(64) >>>(Xc, SQ, C8);
        else
            knn_mma2<128><<<kg, 256, knn2_smem(128)>>>(Xc, SQ, C8);
        packsplit_k<<<(2*O*2*C + 255)/256, 256>>>(W, O, C, Wb);
        dim3 gg((2*O)/128, (B_*N_)/128, 1);
        gemm_mmac<<<gg, 256, GSMEM>>>(C/64, C, SEL_ACT, SEL_W,
                                      Xc, 2*C, (size_t)0,
                                      Wb, 2*C, (size_t)0,
                                      Z, 2*O, (size_t)0);
        fix_epi_k<<<dim3(N_, B_), O>>>(Xin, LDF, C, SQ, C8, Z, Fout, O);
    };
    layer_tc(F + 0,   64,  64,  W2, F + 64);    // x2 -> F[:, 64:128]
    layer_tc(F + 64,  64,  128, W3, F + 128);   // x3 -> F[:, 128:256]
    layer_tc(F + 128, 128, 256, W4, F + 256);   // x4 -> F[:, 256:512]

    // ---- final: out = W5 · concat-features, compact HMMA ------------------
    {
        const int C = 512;
        split_hl<<<(512*2*C + 255)/256, 256>>>(W5, C, C, 512, Wb);
        split_hl<<<(B_*N_*2*C + 255)/256, 256>>>(F, LDF, C, B_*N_, Xb);
        dim3 fg(N_/128, 512/128, B_);
        gemm_mmac<<<fg, 256, GSMEM>>>(C/64, C,
                                      SEL_W, SEL_ACT,
                                      Wb, 2*C, (size_t)0,
                                      Xb, 2*C, (size_t)N_ * 2 * C,
                                      out, N_, (size_t)512 * N_);
    }
}

// round 16
// speedup vs baseline: 1.0505x; 1.0505x over previous
#include <cuda_runtime.h>
#include <cuda_bf16.h>
#include <cstdint>
#include <cstddef>

#define B_  8
#define N_  2048
#define LDF 512

// ---------------- scratch (device globals: allocation-free) ----------------
__device__ __align__(16) float g_X0[B_ * N_ * 3];
__device__ __align__(16) float g_F [B_ * N_ * LDF];      // concat features [b][n][512]
__device__ __align__(16) float g_Z [B_ * N_ * LDF];      // z = W' x, rows [m][2O]
__device__ __align__(16) float g_SQ[B_ * N_];
__device__ __align__(16) int   g_ID[B_ * N_ * 4];
__device__ __align__(16) int   g_C8[B_ * N_ * 8];        // knn top-8 candidates
__device__ __align__(16) __nv_bfloat16 g_Xb[B_ * N_ * 1024]; // compact [h|l] of F (final, Kc=1024)
__device__ __align__(16) __nv_bfloat16 g_Xc[B_ * N_ * 256];  // compact [h|l] (knn + z acts)
__device__ __align__(16) __nv_bfloat16 g_Wb[512 * 1536];     // compact [h|l] weights

__device__ __forceinline__ uint32_t s2u(const void* p) {
    uint32_t a;
    asm("{ .reg .u64 t; cvta.to.shared.u64 t, %1; cvt.u32.u64 %0, t; }" : "=r"(a) : "l"(p));
    return a;
}
// ---- cp.async helpers ----
__device__ __forceinline__ void cp16(uint32_t dst, const void* src) {
    asm volatile("cp.async.cg.shared.global [%0], [%1], 16;" :: "r"(dst), "l"(src));
}
#define CP_COMMIT() asm volatile("cp.async.commit_group;" ::: "memory")
#define CP_WAIT1()  asm volatile("cp.async.wait_group 1;" ::: "memory")

// ---------------- transpose x (B,3,N) -> X0 [b][n][3] ----------------
__global__ void tr_x0_k(const float* __restrict__ x, float* __restrict__ X0)
{
    int t = blockIdx.x * blockDim.x + threadIdx.x;
    const int tot = B_ * 3 * N_;
    if (t >= tot) return;
    int b = t / (3 * N_);
    int r = t % (3 * N_);
    int c = r / N_;
    int n = r % N_;
    X0[((size_t)b * N_ + n) * 3 + c] = x[t];
}

// ---------------- squared norms (L1 only) ----------------
__global__ void sqnorm_k(const float* __restrict__ X, int ldx, int C,
                         float* __restrict__ sq)
{
    int w    = (blockIdx.x * blockDim.x + threadIdx.x) >> 5;
    int lane = threadIdx.x & 31;
    if (w >= B_ * N_) return;
    const float* r = X + (size_t)w * ldx;
    float s = 0.f;
    for (int c = lane; c < C; c += 32) { float v = r[c]; s += v * v; }
    #pragma unroll
    for (int o = 16; o; o >>= 1) s += __shfl_xor_sync(0xffffffffu, s, o);
    if (lane == 0) sq[w] = s;
}

// ------ fused: squared norm + compact [h|l] split, one pass over X --------
__global__ void prep_k(const float* __restrict__ X, int ldx, int C,
                       float* __restrict__ sq, __nv_bfloat16* __restrict__ dst)
{
    int w    = (blockIdx.x * blockDim.x + threadIdx.x) >> 5;
    int lane = threadIdx.x & 31;
    if (w >= B_ * N_) return;
    const float* r = X + (size_t)w * ldx;
    __nv_bfloat16* d = dst + (size_t)w * (2 * C);
    float s = 0.f;
    for (int c = lane; c < C; c += 32) {
        float v = r[c];
        s += v * v;
        float h = __bfloat162float(__float2bfloat16(v));
        d[c]     = __float2bfloat16(h);
        d[C + c] = __float2bfloat16(v - h);
    }
    #pragma unroll
    for (int o = 16; o; o >>= 1) s += __shfl_xor_sync(0xffffffffu, s, o);
    if (lane == 0) sq[w] = s;
}

// ------ fused: pack W (O x 2C) -> W' (2O x C) AND compact [h|l] split -----
__global__ void packsplit_k(const float* __restrict__ W, int O, int C,
                            __nv_bfloat16* __restrict__ dst)
{
    int t = blockIdx.x * blockDim.x + threadIdx.x;
    int Kc = 2 * C;
    int tot = 2 * O * Kc;
    if (t >= tot) return;
    int col = t % Kc;
    int r   = t / Kc;
    int c   = (col < C) ? col : col - C;
    float x = (r < O) ? W[r * (2*C) + c] : W[(r - O) * (2*C) + C + c];
    float h = __bfloat162float(__float2bfloat16(x));
    float v = (col < C) ? h : (x - h);
    dst[t] = __float2bfloat16(v);
}

// ---------------- top-D insertion (value desc, tie: lower index) ----------
template<int D>
__device__ __forceinline__ void topD_insert(float d, int id, float (&v)[D], int (&ix)[D])
{
    if (d > v[D-1] || (d == v[D-1] && id < ix[D-1])) {
        v[D-1] = d; ix[D-1] = id;
        #pragma unroll
        for (int s = D-1; s > 0; s--) {
            if (v[s] > v[s-1] || (v[s] == v[s-1] && ix[s] < ix[s-1])) {
                float tv = v[s]; v[s] = v[s-1]; v[s-1] = tv;
                int   ti = ix[s]; ix[s] = ix[s-1]; ix[s-1] = ti;
            } else break;
        }
    }
}
__device__ __forceinline__ void top4_insert(float d, int id, float (&v)[4], int (&ix)[4])
{ topD_insert<4>(d, id, v, ix); }

// ---------------- fused KNN for C=3 (fp32-exact) --------------------------
__global__ __launch_bounds__(256) void knn3_kernel(const float* __restrict__ X,
                                                   const float* __restrict__ sq,
                                                   int* __restrict__ out_idx)
{
    constexpr int C = 3, QROW = 68;
    __shared__ __align__(16) float pool[64 * 64 * 2];
    float* Qs = pool;
    float* Ks = pool + C * QROW;

    const int b  = blockIdx.y;
    const int q0 = blockIdx.x * 64;
    const int t  = threadIdx.x;
    const int tx = t & 15, ty = t >> 4;
    const size_t rb = (size_t)b * N_;

    for (int f = t; f < 64 * C; f += 256) {
        int c = f % C, m = f / C;
        Qs[c*QROW + m] = X[(rb + q0 + m) * 3 + c];
    }

    float sqq[4];
    #pragma unroll
    for (int i = 0; i < 4; i++) sqq[i] = sq[rb + q0 + ty*4 + i];

    float bv[4][4]; int bix[4][4];
    #pragma unroll
    for (int i = 0; i < 4; i++)
        #pragma unroll
        for (int j = 0; j < 4; j++) { bv[i][j] = -3.4e38f; bix[i][j] = 0x7fffffff; }

    for (int kb = 0; kb < N_; kb += 64) {
        float acc[4][4];
        #pragma unroll
        for (int i = 0; i < 4; i++)
            #pragma unroll
            for (int j = 0; j < 4; j++) acc[i][j] = 0.f;

        __syncthreads();
        for (int f = t; f < 64 * C; f += 256) {
            int c = f % C, m = f / C;
            Ks[c*QROW + m] = X[(rb + kb + m) * 3 + c];
        }
        __syncthreads();
        #pragma unroll
        for (int c = 0; c < C; c++) {
            float4 q4 = *(const float4*)&Qs[c*QROW + ty*4];
            float4 k4 = *(const float4*)&Ks[c*QROW + tx*4];
            float qa[4] = {q4.x, q4.y, q4.z, q4.w};
            float ka[4] = {k4.x, k4.y, k4.z, k4.w};
            #pragma unroll
            for (int i = 0; i < 4; i++)
                #pragma unroll
                for (int j = 0; j < 4; j++)
                    acc[i][j] += qa[i] * ka[j];
        }

        float sqk[4];
        #pragma unroll
        for (int j = 0; j < 4; j++) sqk[j] = sq[rb + kb + tx*4 + j];

        #pragma unroll
        for (int i = 0; i < 4; i++)
            #pragma unroll
            for (int j = 0; j < 4; j++) {
                float d = 2.0f * acc[i][j] - sqq[i] - sqk[j];
                top4_insert(d, kb + tx*4 + j, bv[i], bix[i]);
            }
    }

    __syncthreads();
    float* cv = pool;
    int*   ci = (int*)(pool + 64 * 64);
    #pragma unroll
    for (int qi = 0; qi < 4; qi++) {
        int base = (ty*4 + qi) * 64 + tx * 4;
        #pragma unroll
        for (int r = 0; r < 4; r++) { cv[base + r] = bv[qi][r]; ci[base + r] = bix[qi][r]; }
    }
    __syncthreads();
    if (t < 64) {
        float v4[4]; int i4[4];
        #pragma unroll
        for (int r = 0; r < 4; r++) { v4[r] = -3.4e38f; i4[r] = 0x7fffffff; }
        for (int j = 0; j < 64; j++)
            top4_insert(cv[t*64 + j], ci[t*64 + j], v4, i4);
        int* op = out_idx + (rb + q0 + t) * 4;
        op[0] = i4[0]; op[1] = i4[1]; op[2] = i4[2]; op[3] = i4[3];
    }
}

// ---- L1 edge-conv, fully fused (C=3): z inline + max/relu + dual write ---
__global__ void edge3_k(const float* __restrict__ X0, const float* __restrict__ W1,
                        const int* __restrict__ idx,
                        float* __restrict__ Fo, __nv_bfloat16* __restrict__ Xb)
{
    const int b = blockIdx.y, n = blockIdx.x;
    const size_t rb = (size_t)b * N_;
    const size_t w = rb + n;
    const int o = threadIdx.x;               // 64 threads
    int4 id = *(const int4*)(idx + w * 4);

    const float* wr = W1 + o * 6;
    float wn0 = wr[0], wn1 = wr[1], wn2 = wr[2];
    float wc0 = wr[3], wc1 = wr[4], wc2 = wr[5];

    const float* p0 = X0 + (rb + id.x) * 3;
    const float* p1 = X0 + (rb + id.y) * 3;
    const float* p2 = X0 + (rb + id.z) * 3;
    const float* p3 = X0 + (rb + id.w) * 3;
    float z0 = wn0*p0[0] + wn1*p0[1] + wn2*p0[2];
    float z1 = wn0*p1[0] + wn1*p1[1] + wn2*p1[2];
    float z2 = wn0*p2[0] + wn1*p2[1] + wn2*p2[2];
    float z3 = wn0*p3[0] + wn1*p3[1] + wn2*p3[2];
    const float* pc = X0 + w * 3;
    float zc = wc0*pc[0] + wc1*pc[1] + wc2*pc[2];

    float m = fmaxf(fmaxf(z0, z1), fmaxf(z2, z3));
    float v = fmaxf(m + zc, 0.f);
    Fo[w * LDF + o] = v;
    float h = __bfloat162float(__float2bfloat16(v));
    Xb[w * 1024 + o]       = __float2bfloat16(h);
    Xb[w * 1024 + 512 + o] = __float2bfloat16(v - h);
}

// ---------------- HMMA helpers ----------------
__device__ __forceinline__ void ldmx4(uint32_t (&r)[4], uint32_t addr)
{
    asm volatile("ldmatrix.sync.aligned.m8n8.x4.shared.b16 {%0,%1,%2,%3}, [%4];"
                 : "=r"(r[0]), "=r"(r[1]), "=r"(r[2]), "=r"(r[3]) : "r"(addr));
}
__device__ __forceinline__ void mma16816(float (&d)[4], const uint32_t (&a)[4],
                                         uint32_t b0, uint32_t b1)
{
    asm volatile(
        "mma.sync.aligned.m16n8k16.row.col.f32.bf16.bf16.f32 "
        "{%0,%1,%2,%3}, {%4,%5,%6,%7}, {%8,%9}, {%0,%1,%2,%3};"
        : "+f"(d[0]), "+f"(d[1]), "+f"(d[2]), "+f"(d[3])
        : "r"(a[0]), "r"(a[1]), "r"(a[2]), "r"(a[3]), "r"(b0), "r"(b1));
}

// ------- compact split: fp32 -> [h | l] bf16 limbs (W5 only) --------------
__global__ void split_hl(const float* __restrict__ src, int lds, int C, int R,
                         __nv_bfloat16* __restrict__ dst)
{
    int t = blockIdx.x * blockDim.x + threadIdx.x;
    int Kc = 2 * C;
    int tot = R * Kc;
    if (t >= tot) return;
    int col = t % Kc;
    int r   = t / Kc;
    int c   = (col < C) ? col : col - C;
    float x = src[(size_t)r * lds + c];
    float h = __bfloat162float(__float2bfloat16(x));
    float v = (col < C) ? h : (x - h);
    dst[t] = __float2bfloat16(v);
}

// ===== HMMA KNN on compact [h|l]: 3-term expansion via chunk addressing ===
template<int C>
__global__ __launch_bounds__(256) void knn_mma2(const __nv_bfloat16* __restrict__ XC,
                                                const float* __restrict__ sq,
                                                int* __restrict__ cand)
{
    constexpr int Kc    = 2 * C;
    constexpr int AKROW = Kc + 8;
    constexpr int BSTG  = 128 * AKROW;
    constexpr int NEXP  = (3 * C) / 64;
    constexpr int NBUF  = (C == 64) ? 3 : 2;
    constexpr int NT    = N_ / 128;
    constexpr int NCP   = Kc / 16;
    extern __shared__ __align__(16) float knnpool[];
    __nv_bfloat16* As = (__nv_bfloat16*)knnpool;
    __nv_bfloat16* Bs = As + BSTG;

    int AOFF[NEXP], BOFF[NEXP];
    if constexpr (C == 64) {
        AOFF[0] = 0;  AOFF[1] = 0;   AOFF[2] = 64;
        BOFF[0] = 0;  BOFF[1] = 64;  BOFF[2] = 0;
    } else {
        AOFF[0] = 0;   AOFF[1] = 64;  AOFF[2] = 0;   AOFF[3] = 64;  AOFF[4] = 128; AOFF[5] = 192;
        BOFF[0] = 0;   BOFF[1] = 64;  BOFF[2] = 128; BOFF[3] = 192; BOFF[4] = 0;   BOFF[5] = 64;
    }

    const int b  = blockIdx.y;
    const int q0 = blockIdx.x * 128;
    const size_t rb = (size_t)b * N_;
    const int t = threadIdx.x, wid = t >> 5, lane = t & 31;
    const int wm = wid & 1, wn = wid >> 1;
    const int gid = lane >> 2, tig = lane & 3;
    const uint32_t uA = s2u(As), uB = s2u(Bs);

    for (int idx = t; idx < 128 * (Kc / 8); idx += 256) {
        int r = idx / (Kc / 8), c8 = idx % (Kc / 8);
        uint4 v = *(const uint4*)(XC + (rb + q0 + r) * (size_t)Kc + c8 * 8);
        *(uint4*)(As + r * AKROW + c8 * 8) = v;
    }
    __syncthreads();

    const int a_r  = wm * 64 + (lane & 15);
    const int a_c8 = (lane >> 4) * 8;
    const int b_rl = wn * 32 + ((lane >> 4) << 3) + (lane & 7);
    const int b_c8 = ((lane >> 3) & 1) * 8;

    float sqq8[8];
    #pragma unroll
    for (int i = 0; i < 8; i++) {
        int mt = i >> 1, h = i & 1;
        sqq8[i] = sq[rb + q0 + wm * 64 + mt * 16 + h * 8 + gid];
    }

    float bv[8][4]; int bix[8][4];
    #pragma unroll
    for (int i = 0; i < 8; i++)
        #pragma unroll
        for (int j = 0; j < 4; j++) { bv[i][j] = -3.4e38f; bix[i][j] = 0x7fffffff; }

    auto kissue = [&](int kt2) {
        if (kt2 < NT) {
            int s = kt2 % NBUF;
            const __nv_bfloat16* p = XC + (rb + kt2 * 128) * (size_t)Kc;
            uint32_t db = uB + 2u * (s * BSTG);
            #pragma unroll
            for (int q = 0; q < NCP; q++) {
                int idx = t + q * 256;
                int r = idx / (Kc / 8), c8 = idx % (Kc / 8);
                cp16(db + 2u * (r * AKROW + c8 * 8),
                     p + (size_t)r * Kc + c8 * 8);
            }
        }
        CP_COMMIT();
    };

    kissue(0); kissue(1);
    for (int kt = 0; kt < NT; kt++) {
        CP_WAIT1();
        __syncthreads();
        const uint32_t uBs = uB + 2u * ((kt % NBUF) * BSTG);

        float acc[4][4][4];
        #pragma unroll
        for (int mt = 0; mt < 4; mt++)
            #pragma unroll
            for (int nt = 0; nt < 4; nt++)
                #pragma unroll
                for (int e = 0; e < 4; e++) acc[mt][nt][e] = 0.f;

        #pragma unroll
        for (int i = 0; i < NEXP; i++) {
            #pragma unroll
            for (int ks = 0; ks < 64; ks += 16) {
                uint32_t af[4][4], bf[2][4];
                #pragma unroll
                for (int mt = 0; mt < 4; mt++)
                    ldmx4(af[mt], uA + 2u * ((a_r + mt * 16) * AKROW + AOFF[i] + ks + a_c8));
                #pragma unroll
                for (int n2 = 0; n2 < 2; n2++)
                    ldmx4(bf[n2], uBs + 2u * ((b_rl + n2 * 16) * AKROW + BOFF[i] + ks + b_c8));
                #pragma unroll
                for (int mt = 0; mt < 4; mt++)
                    #pragma unroll
                    for (int nt = 0; nt < 4; nt++)
                        mma16816(acc[mt][nt], af[mt],
                                 bf[nt >> 1][(nt & 1) * 2], bf[nt >> 1][(nt & 1) * 2 + 1]);
            }
        }
        if constexpr (NBUF == 2) __syncthreads();
        kissue(kt + 2);

        #pragma unroll
        for (int nt = 0; nt < 4; nt++) {
            int c0 = kt * 128 + wn * 32 + nt * 8 + tig * 2;
            float sk0 = sq[rb + c0], sk1 = sq[rb + c0 + 1];
            #pragma unroll
            for (int mt = 0; mt < 4; mt++)
                #pragma unroll
                for (int e = 0; e < 4; e++) {
                    int i8 = mt * 2 + (e >> 1);
                    float d = 2.0f * acc[mt][nt][e] - sqq8[i8] - ((e & 1) ? sk1 : sk0);
                    top4_insert(d, c0 + (e & 1), bv[i8], bix[i8]);
                }
        }
    }

    __syncthreads();
    float* cv = knnpool;
    int*   ci = (int*)(knnpool + 128 * 64);
    #pragma unroll
    for (int i = 0; i < 8; i++) {
        int mt = i >> 1, h = i & 1;
        int rowL = wm * 64 + mt * 16 + h * 8 + gid;
        int slot = wn * 16 + tig * 4;
        #pragma unroll
        for (int j = 0; j < 4; j++) {
            cv[rowL * 64 + slot + j] = bv[i][j];
            ci[rowL * 64 + slot + j] = bix[i][j];
        }
    }
    __syncthreads();
    if (t < 128) {
        float v8[8]; int i8[8];
        #pragma unroll
        for (int r = 0; r < 8; r++) { v8[r] = -3.4e38f; i8[r] = 0x7fffffff; }
        for (int j = 0; j < 64; j++)
            topD_insert<8>(cv[t * 64 + j], ci[t * 64 + j], v8, i8);
        int* op = cand + (rb + q0 + t) * 8;
        #pragma unroll
        for (int r = 0; r < 8; r++) op[r] = i8[r];
    }
}

static inline int knn2_smem(int C) {
    int Kc = 2 * C, row = Kc + 8;
    int nbuf = (C == 64) ? 3 : 2;
    int tot = (1 + nbuf) * 128 * row * 2;
    int mg = 128 * 64 * 8;
    return tot > mg ? tot : mg;
}

// ==== fused: exact fp32 fixup + edge epilogue + dual fp32/[h|l] write =====
__global__ void fix_epi_k(const float* __restrict__ X, int ldx, int C,
                          const float* __restrict__ sq,
                          const int* __restrict__ cand,
                          const float* __restrict__ Z,
                          float* __restrict__ Fo, int O,
                          __nv_bfloat16* __restrict__ Xb, int fcol0)
{
    __shared__ int sid[4];
    const int b = blockIdx.y, n = blockIdx.x;
    const size_t rb = (size_t)b * N_;
    const size_t w = rb + n;
    const int t = threadIdx.x, lane = t & 31;

    if (t < 32) {
        int id = 0; float d = -3.4e38f;
        if (lane < 8) {
            id = cand[w * 8 + lane];
            const float* qp = X + w * (size_t)ldx;
            const float* kp = X + (rb + id) * (size_t)ldx;
            float dot = 0.f;
            for (int c = 0; c < C; c += 4) {
                float4 a = *(const float4*)(qp + c);
                float4 b2 = *(const float4*)(kp + c);
                dot += a.x * b2.x + a.y * b2.y + a.z * b2.z + a.w * b2.w;
            }
            d = 2.0f * dot - sq[w] - sq[rb + id];
        }
        float v4[4]; int i4[4];
        #pragma unroll
        for (int r = 0; r < 4; r++) { v4[r] = -3.4e38f; i4[r] = 0x7fffffff; }
        #pragma unroll
        for (int j = 0; j < 8; j++) {
            float dj = __shfl_sync(0xffffffffu, d, j);
            int   ij = __shfl_sync(0xffffffffu, id, j);
            top4_insert(dj, ij, v4, i4);
        }
        if (lane == 0) { sid[0] = i4[0]; sid[1] = i4[1]; sid[2] = i4[2]; sid[3] = i4[3]; }
    }
    __syncthreads();
    int4 id = *(int4*)sid;
    const size_t wz = (size_t)(2 * O);
    const float* zb = Z + rb * wz;
    const float* z0 = zb + (size_t)id.x * wz;
    const float* z1 = zb + (size_t)id.y * wz;
    const float* z2 = zb + (size_t)id.z * wz;
    const float* z3 = zb + (size_t)id.w * wz;
    const float* zc = zb + (size_t)n * wz + O;
    float* fo = Fo + w * LDF;
    __nv_bfloat16* xb = Xb + w * 1024 + fcol0;
    for (int o = t; o < O; o += blockDim.x) {
        float m = fmaxf(fmaxf(z0[o], z1[o]), fmaxf(z2[o], z3[o]));
        float v = fmaxf(m + zc[o], 0.f);
        fo[o] = v;
        float h = __bfloat162float(__float2bfloat16(v));
        xb[o]       = __float2bfloat16(h);
        xb[512 + o] = __float2bfloat16(v - h);
    }
}

// ====== HMMA bf16 NT-GEMM on COMPACT [h|l], 3-stage ring (R14 proven) =====
#define KC   64
#define KPAD 8
#define AROW (KC + KPAD)
#define GSTG (128 * AROW)
#define GSMEM (3 * GSTG * 2 * 2)

__global__ __launch_bounds__(256) void gemm_mmac(int tpt, int Cc,
    unsigned selA, unsigned selB,
    const __nv_bfloat16* __restrict__ A, int lda, size_t sA,
    const __nv_bfloat16* __restrict__ B, int ldb, size_t sB,
    float* __restrict__ D, int ldd, size_t sD)
{
    extern __shared__ __align__(16) __nv_bfloat16 gsm[];
    __nv_bfloat16* As = gsm;
    __nv_bfloat16* Bs = gsm + 3 * GSTG;
    const int bz = blockIdx.z;
    A += (size_t)bz * sA;
    B += (size_t)bz * sB;
    D += (size_t)bz * sD;
    const int i0 = blockIdx.y * 128;
    const int j0 = blockIdx.x * 128;
    const int t = threadIdx.x, wid = t >> 5, lane = t & 31;
    const int wm = wid & 1, wn = wid >> 1;
    const int gid = lane >> 2, tig = lane & 3;

    const uint32_t uA = s2u(As), uB = s2u(Bs);

    const int a_r  = wm * 64 + (lane & 15);
    const int a_c8 = (lane >> 4) * 8;
    const int b_r  = wn * 32 + ((lane >> 4) << 3) + (lane & 7);
    const int b_c8 = ((lane >> 3) & 1) * 8;

    float acc[4][4][4];
    #pragma unroll
    for (int mt = 0; mt < 4; mt++)
        #pragma unroll
        for (int nt = 0; nt < 4; nt++)
            #pragma unroll
            for (int e = 0; e < 4; e++) acc[mt][nt][e] = 0.f;

    const int nk = 3 * tpt;

    auto issue = [&](int k2) {
        if (k2 < nk) {
            int s = k2 % 3;
            int tb = k2 / tpt, ic = k2 % tpt;
            int offA = ic * 64 + (int)((selA >> tb) & 1u) * Cc;
            int offB = ic * 64 + (int)((selB >> tb) & 1u) * Cc;
            const __nv_bfloat16* Ag = A + (size_t)i0 * lda + offA;
            const __nv_bfloat16* Bg = B + (size_t)j0 * ldb + offB;
            uint32_t da = uA + 2u * (s * GSTG);
            uint32_t db = uB + 2u * (s * GSTG);
            #pragma unroll
            for (int q = 0; q < 4; q++) {
                int idx = t + q * 256;
                int r = idx >> 3, c8 = idx & 7;
                cp16(da + 2u * (r * AROW + c8 * 8), Ag + (size_t)r * lda + c8 * 8);
                cp16(db + 2u * (r * AROW + c8 * 8), Bg + (size_t)r * ldb + c8 * 8);
            }
        }
        CP_COMMIT();
    };

    issue(0); issue(1);
    for (int k = 0; k < nk; k++) {
        CP_WAIT1();
        __syncthreads();
        const int s = k % 3;
        const uint32_t uAs = uA + 2u * (s * GSTG);
        const uint32_t uBs = uB + 2u * (s * GSTG);
        #pragma unroll
        for (int ks = 0; ks < KC; ks += 16) {
            uint32_t af[4][4], bf[2][4];
            #pragma unroll
            for (int mt = 0; mt < 4; mt++)
                ldmx4(af[mt], uAs + 2u * ((a_r + mt * 16) * AROW + ks + a_c8));
            #pragma unroll
            for (int n2 = 0; n2 < 2; n2++)
                ldmx4(bf[n2], uBs + 2u * ((b_r + n2 * 16) * AROW + ks + b_c8));
            #pragma unroll
            for (int mt = 0; mt < 4; mt++)
                #pragma unroll
                for (int nt = 0; nt < 4; nt++)
                    mma16816(acc[mt][nt], af[mt],
                             bf[nt >> 1][(nt & 1) * 2], bf[nt >> 1][(nt & 1) * 2 + 1]);
        }
        issue(k + 2);
    }

    #pragma unroll
    for (int mt = 0; mt < 4; mt++) {
        int r = i0 + wm * 64 + mt * 16 + gid;
        #pragma unroll
        for (int nt = 0; nt < 4; nt++) {
            int c = j0 + wn * 32 + nt * 8 + tig * 2;
            *(float2*)&D[(size_t)r * ldd + c]       = make_float2(acc[mt][nt][0], acc[mt][nt][1]);
            *(float2*)&D[(size_t)(r + 8) * ldd + c] = make_float2(acc[mt][nt][2], acc[mt][nt][3]);
        }
    }
}

// ---------------- orchestration ----------------
extern "C" void kernel_launch(void* const* d_in, const int* in_sizes, int n_in,
                              void* d_out, int out_size)
{
    const float* x  = (const float*)d_in[0];
    const float* W1 = (const float*)d_in[1];
    const float* W2 = (const float*)d_in[2];
    const float* W3 = (const float*)d_in[3];
    const float* W4 = (const float*)d_in[4];
    const float* W5 = (const float*)d_in[5];
    float* out = (float*)d_out;

    void* p;
    cudaGetSymbolAddress(&p, g_X0);  float* X0 = (float*)p;
    cudaGetSymbolAddress(&p, g_F );  float* F  = (float*)p;
    cudaGetSymbolAddress(&p, g_Z );  float* Z  = (float*)p;
    cudaGetSymbolAddress(&p, g_SQ);  float* SQ = (float*)p;
    cudaGetSymbolAddress(&p, g_ID);  int*   ID = (int*)p;
    cudaGetSymbolAddress(&p, g_C8);  int*   C8 = (int*)p;
    cudaGetSymbolAddress(&p, g_Xb);  __nv_bfloat16* Xb = (__nv_bfloat16*)p;
    cudaGetSymbolAddress(&p, g_Xc);  __nv_bfloat16* Xc = (__nv_bfloat16*)p;
    cudaGetSymbolAddress(&p, g_Wb);  __nv_bfloat16* Wb = (__nv_bfloat16*)p;

    cudaFuncSetAttribute(knn_mma2<64>,
        cudaFuncAttributeMaxDynamicSharedMemorySize, knn2_smem(64));
    cudaFuncSetAttribute(knn_mma2<128>,
        cudaFuncAttributeMaxDynamicSharedMemorySize, knn2_smem(128));
    cudaFuncSetAttribute(gemm_mmac,
        cudaFuncAttributeMaxDynamicSharedMemorySize, GSMEM);

    // sel bits per term (0=h,1=l): activations {h,h,l} -> 0b100,
    //                              weights     {h,l,h} -> 0b010
    const unsigned SEL_ACT = 0b100u;
    const unsigned SEL_W   = 0b010u;

    tr_x0_k<<<(B_*3*N_ + 255)/256, 256>>>(x, X0);

    // ---- layer 1: fp32 knn (C=3) + fully fused edge-conv (dual write)
    {
        sqnorm_k<<<(B_*N_*32)/256, 256>>>(X0, 3, 3, SQ);
        knn3_kernel<<<dim3(N_/64, B_), 256>>>(X0, SQ, ID);
        edge3_k<<<dim3(N_, B_), 64>>>(X0, W1, ID, F + 0, Xb);
    }

    // ---- layers 2-4: HMMA knn + compact HMMA z-GEMM + fused epilogue ----
    auto layer_tc = [&](const float* Xin, int C, int O, const float* W,
                        float* Fout, int fcol0) {
        prep_k<<<(B_*N_*32)/256, 256>>>(Xin, LDF, C, SQ, Xc);
        dim3 kg(N_/128, B_);
        if (C == 64)
            knn_mma2<64> <<<kg, 256, knn2_smem(64) >>>(Xc, SQ, C8);
        else
            knn_mma2<128><<<kg, 256, knn2_smem(128)>>>(Xc, SQ, C8);
        packsplit_k<<<(2*O*2*C + 255)/256, 256>>>(W, O, C, Wb);
        dim3 gg((2*O)/128, (B_*N_)/128, 1);
        gemm_mmac<<<gg, 256, GSMEM>>>(C/64, C, SEL_ACT, SEL_W,
                                      Xc, 2*C, (size_t)0,
                                      Wb, 2*C, (size_t)0,
                                      Z, 2*O, (size_t)0);
        fix_epi_k<<<dim3(N_, B_), O>>>(Xin, LDF, C, SQ, C8, Z, Fout, O, Xb, fcol0);
    };
    layer_tc(F + 0,   64,  64,  W2, F + 64,  64);    // x2 -> F[:, 64:128]
    layer_tc(F + 64,  64,  128, W3, F + 128, 128);   // x3 -> F[:, 128:256]
    layer_tc(F + 128, 128, 256, W4, F + 256, 256);   // x4 -> F[:, 256:512]

    // ---- final: out = W5 · concat-features (Xb already populated) --------
    {
        const int C = 512;
        split_hl<<<(512*2*C + 255)/256, 256>>>(W5, C, C, 512, Wb);
        dim3 fg(N_/128, 512/128, B_);
        gemm_mmac<<<fg, 256, GSMEM>>>(C/64, C,
                                      SEL_W, SEL_ACT,
                                      Wb, 2*C, (size_t)0,
                                      Xb, 2*C, (size_t)N_ * 2 * C,
                                      out, N_, (size_t)512 * N_);
    }
}

// round 17
// speedup vs baseline: 1.0614x; 1.0104x over previous
#include <cuda_runtime.h>
#include <cuda_bf16.h>
#include <cstdint>
#include <cstddef>

#define B_  8
#define N_  2048
#define LDF 512

// ---------------- scratch (device globals: allocation-free) ----------------
__device__ __align__(16) float g_X0[B_ * N_ * 3];
__device__ __align__(16) float g_F [B_ * N_ * LDF];      // concat features [b][n][512]
__device__ __align__(16) float g_Z [B_ * N_ * LDF];      // z = W' x, rows [m][2O]
__device__ __align__(16) float g_SQ [B_ * N_];           // norm ping
__device__ __align__(16) float g_SQ2[B_ * N_];           // norm pong
__device__ __align__(16) int   g_ID[B_ * N_ * 4];
__device__ __align__(16) int   g_C8[B_ * N_ * 8];        // knn top-8 candidates
__device__ __align__(16) __nv_bfloat16 g_Xb[B_ * N_ * 1024]; // compact [h|l] of F (final)
__device__ __align__(16) __nv_bfloat16 g_Xc[B_ * N_ * 256];  // compact [h|l] (knn + z acts)
__device__ __align__(16) __nv_bfloat16 g_Wb[512 * 1536];     // compact [h|l] weights

__device__ __forceinline__ uint32_t s2u(const void* p) {
    uint32_t a;
    asm("{ .reg .u64 t; cvta.to.shared.u64 t, %1; cvt.u32.u64 %0, t; }" : "=r"(a) : "l"(p));
    return a;
}
// ---- cp.async helpers ----
__device__ __forceinline__ void cp16(uint32_t dst, const void* src) {
    asm volatile("cp.async.cg.shared.global [%0], [%1], 16;" :: "r"(dst), "l"(src));
}
#define CP_COMMIT() asm volatile("cp.async.commit_group;" ::: "memory")
#define CP_WAIT1()  asm volatile("cp.async.wait_group 1;" ::: "memory")

// ---------------- transpose x (B,3,N) -> X0 [b][n][3] ----------------
__global__ void tr_x0_k(const float* __restrict__ x, float* __restrict__ X0)
{
    int t = blockIdx.x * blockDim.x + threadIdx.x;
    const int tot = B_ * 3 * N_;
    if (t >= tot) return;
    int b = t / (3 * N_);
    int r = t % (3 * N_);
    int c = r / N_;
    int n = r % N_;
    X0[((size_t)b * N_ + n) * 3 + c] = x[t];
}

// ---------------- squared norms (L1 only) ----------------
__global__ void sqnorm_k(const float* __restrict__ X, int ldx, int C,
                         float* __restrict__ sq)
{
    int w    = (blockIdx.x * blockDim.x + threadIdx.x) >> 5;
    int lane = threadIdx.x & 31;
    if (w >= B_ * N_) return;
    const float* r = X + (size_t)w * ldx;
    float s = 0.f;
    for (int c = lane; c < C; c += 32) { float v = r[c]; s += v * v; }
    #pragma unroll
    for (int o = 16; o; o >>= 1) s += __shfl_xor_sync(0xffffffffu, s, o);
    if (lane == 0) sq[w] = s;
}

// ------ fused: pack W (O x 2C) -> W' (2O x C) AND compact [h|l] split -----
__global__ void packsplit_k(const float* __restrict__ W, int O, int C,
                            __nv_bfloat16* __restrict__ dst)
{
    int t = blockIdx.x * blockDim.x + threadIdx.x;
    int Kc = 2 * C;
    int tot = 2 * O * Kc;
    if (t >= tot) return;
    int col = t % Kc;
    int r   = t / Kc;
    int c   = (col < C) ? col : col - C;
    float x = (r < O) ? W[r * (2*C) + c] : W[(r - O) * (2*C) + C + c];
    float h = __bfloat162float(__float2bfloat16(x));
    float v = (col < C) ? h : (x - h);
    dst[t] = __float2bfloat16(v);
}

// ---------------- top-D insertion (value desc, tie: lower index) ----------
template<int D>
__device__ __forceinline__ void topD_insert(float d, int id, float (&v)[D], int (&ix)[D])
{
    if (d > v[D-1] || (d == v[D-1] && id < ix[D-1])) {
        v[D-1] = d; ix[D-1] = id;
        #pragma unroll
        for (int s = D-1; s > 0; s--) {
            if (v[s] > v[s-1] || (v[s] == v[s-1] && ix[s] < ix[s-1])) {
                float tv = v[s]; v[s] = v[s-1]; v[s-1] = tv;
                int   ti = ix[s]; ix[s] = ix[s-1]; ix[s-1] = ti;
            } else break;
        }
    }
}
__device__ __forceinline__ void top4_insert(float d, int id, float (&v)[4], int (&ix)[4])
{ topD_insert<4>(d, id, v, ix); }

// ---------------- fused KNN for C=3 (fp32-exact) --------------------------
__global__ __launch_bounds__(256) void knn3_kernel(const float* __restrict__ X,
                                                   const float* __restrict__ sq,
                                                   int* __restrict__ out_idx)
{
    constexpr int C = 3, QROW = 68;
    __shared__ __align__(16) float pool[64 * 64 * 2];
    float* Qs = pool;
    float* Ks = pool + C * QROW;

    const int b  = blockIdx.y;
    const int q0 = blockIdx.x * 64;
    const int t  = threadIdx.x;
    const int tx = t & 15, ty = t >> 4;
    const size_t rb = (size_t)b * N_;

    for (int f = t; f < 64 * C; f += 256) {
        int c = f % C, m = f / C;
        Qs[c*QROW + m] = X[(rb + q0 + m) * 3 + c];
    }

    float sqq[4];
    #pragma unroll
    for (int i = 0; i < 4; i++) sqq[i] = sq[rb + q0 + ty*4 + i];

    float bv[4][4]; int bix[4][4];
    #pragma unroll
    for (int i = 0; i < 4; i++)
        #pragma unroll
        for (int j = 0; j < 4; j++) { bv[i][j] = -3.4e38f; bix[i][j] = 0x7fffffff; }

    for (int kb = 0; kb < N_; kb += 64) {
        float acc[4][4];
        #pragma unroll
        for (int i = 0; i < 4; i++)
            #pragma unroll
            for (int j = 0; j < 4; j++) acc[i][j] = 0.f;

        __syncthreads();
        for (int f = t; f < 64 * C; f += 256) {
            int c = f % C, m = f / C;
            Ks[c*QROW + m] = X[(rb + kb + m) * 3 + c];
        }
        __syncthreads();
        #pragma unroll
        for (int c = 0; c < C; c++) {
            float4 q4 = *(const float4*)&Qs[c*QROW + ty*4];
            float4 k4 = *(const float4*)&Ks[c*QROW + tx*4];
            float qa[4] = {q4.x, q4.y, q4.z, q4.w};
            float ka[4] = {k4.x, k4.y, k4.z, k4.w};
            #pragma unroll
            for (int i = 0; i < 4; i++)
                #pragma unroll
                for (int j = 0; j < 4; j++)
                    acc[i][j] += qa[i] * ka[j];
        }

        float sqk[4];
        #pragma unroll
        for (int j = 0; j < 4; j++) sqk[j] = sq[rb + kb + tx*4 + j];

        #pragma unroll
        for (int i = 0; i < 4; i++)
            #pragma unroll
            for (int j = 0; j < 4; j++) {
                float d = 2.0f * acc[i][j] - sqq[i] - sqk[j];
                top4_insert(d, kb + tx*4 + j, bv[i], bix[i]);
            }
    }

    __syncthreads();
    float* cv = pool;
    int*   ci = (int*)(pool + 64 * 64);
    #pragma unroll
    for (int qi = 0; qi < 4; qi++) {
        int base = (ty*4 + qi) * 64 + tx * 4;
        #pragma unroll
        for (int r = 0; r < 4; r++) { cv[base + r] = bv[qi][r]; ci[base + r] = bix[qi][r]; }
    }
    __syncthreads();
    if (t < 64) {
        float v4[4]; int i4[4];
        #pragma unroll
        for (int r = 0; r < 4; r++) { v4[r] = -3.4e38f; i4[r] = 0x7fffffff; }
        for (int j = 0; j < 64; j++)
            top4_insert(cv[t*64 + j], ci[t*64 + j], v4, i4);
        int* op = out_idx + (rb + q0 + t) * 4;
        op[0] = i4[0]; op[1] = i4[1]; op[2] = i4[2]; op[3] = i4[3];
    }
}

// ---- L1 edge-conv, fully fused: z inline + max/relu + F/Xb/Xc/SQ write ---
__global__ void edge3_k(const float* __restrict__ X0, const float* __restrict__ W1,
                        const int* __restrict__ idx,
                        float* __restrict__ Fo, __nv_bfloat16* __restrict__ Xb,
                        __nv_bfloat16* __restrict__ Xc, float* __restrict__ sqOut)
{
    __shared__ float wsum[2];
    const int b = blockIdx.y, n = blockIdx.x;
    const size_t rb = (size_t)b * N_;
    const size_t w = rb + n;
    const int o = threadIdx.x;               // 64 threads
    int4 id = *(const int4*)(idx + w * 4);

    const float* wr = W1 + o * 6;
    float wn0 = wr[0], wn1 = wr[1], wn2 = wr[2];
    float wc0 = wr[3], wc1 = wr[4], wc2 = wr[5];

    const float* p0 = X0 + (rb + id.x) * 3;
    const float* p1 = X0 + (rb + id.y) * 3;
    const float* p2 = X0 + (rb + id.z) * 3;
    const float* p3 = X0 + (rb + id.w) * 3;
    float z0 = wn0*p0[0] + wn1*p0[1] + wn2*p0[2];
    float z1 = wn0*p1[0] + wn1*p1[1] + wn2*p1[2];
    float z2 = wn0*p2[0] + wn1*p2[1] + wn2*p2[2];
    float z3 = wn0*p3[0] + wn1*p3[1] + wn2*p3[2];
    const float* pc = X0 + w * 3;
    float zc = wc0*pc[0] + wc1*pc[1] + wc2*pc[2];

    float m = fmaxf(fmaxf(z0, z1), fmaxf(z2, z3));
    float v = fmaxf(m + zc, 0.f);
    Fo[w * LDF + o] = v;
    float h = __bfloat162float(__float2bfloat16(v));
    float l = v - h;
    Xb[w * 1024 + o]       = __float2bfloat16(h);
    Xb[w * 1024 + 512 + o] = __float2bfloat16(l);
    Xc[w * 128 + o]        = __float2bfloat16(h);
    Xc[w * 128 + 64 + o]   = __float2bfloat16(l);

    float s = v * v;
    #pragma unroll
    for (int off = 16; off; off >>= 1) s += __shfl_xor_sync(0xffffffffu, s, off);
    if ((o & 31) == 0) wsum[o >> 5] = s;
    __syncthreads();
    if (o == 0) sqOut[w] = wsum[0] + wsum[1];
}

// ---------------- HMMA helpers ----------------
__device__ __forceinline__ void ldmx4(uint32_t (&r)[4], uint32_t addr)
{
    asm volatile("ldmatrix.sync.aligned.m8n8.x4.shared.b16 {%0,%1,%2,%3}, [%4];"
                 : "=r"(r[0]), "=r"(r[1]), "=r"(r[2]), "=r"(r[3]) : "r"(addr));
}
__device__ __forceinline__ void mma16816(float (&d)[4], const uint32_t (&a)[4],
                                         uint32_t b0, uint32_t b1)
{
    asm volatile(
        "mma.sync.aligned.m16n8k16.row.col.f32.bf16.bf16.f32 "
        "{%0,%1,%2,%3}, {%4,%5,%6,%7}, {%8,%9}, {%0,%1,%2,%3};"
        : "+f"(d[0]), "+f"(d[1]), "+f"(d[2]), "+f"(d[3])
        : "r"(a[0]), "r"(a[1]), "r"(a[2]), "r"(a[3]), "r"(b0), "r"(b1));
}

// ------- compact split: fp32 -> [h | l] bf16 limbs (W5 only) --------------
__global__ void split_hl(const float* __restrict__ src, int lds, int C, int R,
                         __nv_bfloat16* __restrict__ dst)
{
    int t = blockIdx.x * blockDim.x + threadIdx.x;
    int Kc = 2 * C;
    int tot = R * Kc;
    if (t >= tot) return;
    int col = t % Kc;
    int r   = t / Kc;
    int c   = (col < C) ? col : col - C;
    float x = src[(size_t)r * lds + c];
    float h = __bfloat162float(__float2bfloat16(x));
    float v = (col < C) ? h : (x - h);
    dst[t] = __float2bfloat16(v);
}

// ===== HMMA KNN on compact [h|l]: 3-term expansion via chunk addressing ===
template<int C>
__global__ __launch_bounds__(256) void knn_mma2(const __nv_bfloat16* __restrict__ XC,
                                                const float* __restrict__ sq,
                                                int* __restrict__ cand)
{
    constexpr int Kc    = 2 * C;
    constexpr int AKROW = Kc + 8;
    constexpr int BSTG  = 128 * AKROW;
    constexpr int NEXP  = (3 * C) / 64;
    constexpr int NBUF  = (C == 64) ? 3 : 2;
    constexpr int NT    = N_ / 128;
    constexpr int NCP   = Kc / 16;
    extern __shared__ __align__(16) float knnpool[];
    __nv_bfloat16* As = (__nv_bfloat16*)knnpool;
    __nv_bfloat16* Bs = As + BSTG;

    int AOFF[NEXP], BOFF[NEXP];
    if constexpr (C == 64) {
        AOFF[0] = 0;  AOFF[1] = 0;   AOFF[2] = 64;
        BOFF[0] = 0;  BOFF[1] = 64;  BOFF[2] = 0;
    } else {
        AOFF[0] = 0;   AOFF[1] = 64;  AOFF[2] = 0;   AOFF[3] = 64;  AOFF[4] = 128; AOFF[5] = 192;
        BOFF[0] = 0;   BOFF[1] = 64;  BOFF[2] = 128; BOFF[3] = 192; BOFF[4] = 0;   BOFF[5] = 64;
    }

    const int b  = blockIdx.y;
    const int q0 = blockIdx.x * 128;
    const size_t rb = (size_t)b * N_;
    const int t = threadIdx.x, wid = t >> 5, lane = t & 31;
    const int wm = wid & 1, wn = wid >> 1;
    const int gid = lane >> 2, tig = lane & 3;
    const uint32_t uA = s2u(As), uB = s2u(Bs);

    for (int idx = t; idx < 128 * (Kc / 8); idx += 256) {
        int r = idx / (Kc / 8), c8 = idx % (Kc / 8);
        uint4 v = *(const uint4*)(XC + (rb + q0 + r) * (size_t)Kc + c8 * 8);
        *(uint4*)(As + r * AKROW + c8 * 8) = v;
    }
    __syncthreads();

    const int a_r  = wm * 64 + (lane & 15);
    const int a_c8 = (lane >> 4) * 8;
    const int b_rl = wn * 32 + ((lane >> 4) << 3) + (lane & 7);
    const int b_c8 = ((lane >> 3) & 1) * 8;

    float sqq8[8];
    #pragma unroll
    for (int i = 0; i < 8; i++) {
        int mt = i >> 1, h = i & 1;
        sqq8[i] = sq[rb + q0 + wm * 64 + mt * 16 + h * 8 + gid];
    }

    float bv[8][4]; int bix[8][4];
    #pragma unroll
    for (int i = 0; i < 8; i++)
        #pragma unroll
        for (int j = 0; j < 4; j++) { bv[i][j] = -3.4e38f; bix[i][j] = 0x7fffffff; }

    auto kissue = [&](int kt2) {
        if (kt2 < NT) {
            int s = kt2 % NBUF;
            const __nv_bfloat16* p = XC + (rb + kt2 * 128) * (size_t)Kc;
            uint32_t db = uB + 2u * (s * BSTG);
            #pragma unroll
            for (int q = 0; q < NCP; q++) {
                int idx = t + q * 256;
                int r = idx / (Kc / 8), c8 = idx % (Kc / 8);
                cp16(db + 2u * (r * AKROW + c8 * 8),
                     p + (size_t)r * Kc + c8 * 8);
            }
        }
        CP_COMMIT();
    };

    kissue(0); kissue(1);
    for (int kt = 0; kt < NT; kt++) {
        CP_WAIT1();
        __syncthreads();
        const uint32_t uBs = uB + 2u * ((kt % NBUF) * BSTG);

        float acc[4][4][4];
        #pragma unroll
        for (int mt = 0; mt < 4; mt++)
            #pragma unroll
            for (int nt = 0; nt < 4; nt++)
                #pragma unroll
                for (int e = 0; e < 4; e++) acc[mt][nt][e] = 0.f;

        #pragma unroll
        for (int i = 0; i < NEXP; i++) {
            #pragma unroll
            for (int ks = 0; ks < 64; ks += 16) {
                uint32_t af[4][4], bf[2][4];
                #pragma unroll
                for (int mt = 0; mt < 4; mt++)
                    ldmx4(af[mt], uA + 2u * ((a_r + mt * 16) * AKROW + AOFF[i] + ks + a_c8));
                #pragma unroll
                for (int n2 = 0; n2 < 2; n2++)
                    ldmx4(bf[n2], uBs + 2u * ((b_rl + n2 * 16) * AKROW + BOFF[i] + ks + b_c8));
                #pragma unroll
                for (int mt = 0; mt < 4; mt++)
                    #pragma unroll
                    for (int nt = 0; nt < 4; nt++)
                        mma16816(acc[mt][nt], af[mt],
                                 bf[nt >> 1][(nt & 1) * 2], bf[nt >> 1][(nt & 1) * 2 + 1]);
            }
        }
        if constexpr (NBUF == 2) __syncthreads();
        kissue(kt + 2);

        #pragma unroll
        for (int nt = 0; nt < 4; nt++) {
            int c0 = kt * 128 + wn * 32 + nt * 8 + tig * 2;
            float sk0 = sq[rb + c0], sk1 = sq[rb + c0 + 1];
            #pragma unroll
            for (int mt = 0; mt < 4; mt++)
                #pragma unroll
                for (int e = 0; e < 4; e++) {
                    int i8 = mt * 2 + (e >> 1);
                    float d = 2.0f * acc[mt][nt][e] - sqq8[i8] - ((e & 1) ? sk1 : sk0);
                    top4_insert(d, c0 + (e & 1), bv[i8], bix[i8]);
                }
        }
    }

    __syncthreads();
    float* cv = knnpool;
    int*   ci = (int*)(knnpool + 128 * 64);
    #pragma unroll
    for (int i = 0; i < 8; i++) {
        int mt = i >> 1, h = i & 1;
        int rowL = wm * 64 + mt * 16 + h * 8 + gid;
        int slot = wn * 16 + tig * 4;
        #pragma unroll
        for (int j = 0; j < 4; j++) {
            cv[rowL * 64 + slot + j] = bv[i][j];
            ci[rowL * 64 + slot + j] = bix[i][j];
        }
    }
    __syncthreads();
    if (t < 128) {
        float v8[8]; int i8[8];
        #pragma unroll
        for (int r = 0; r < 8; r++) { v8[r] = -3.4e38f; i8[r] = 0x7fffffff; }
        for (int j = 0; j < 64; j++)
            topD_insert<8>(cv[t * 64 + j], ci[t * 64 + j], v8, i8);
        int* op = cand + (rb + q0 + t) * 8;
        #pragma unroll
        for (int r = 0; r < 8; r++) op[r] = i8[r];
    }
}

static inline int knn2_smem(int C) {
    int Kc = 2 * C, row = Kc + 8;
    int nbuf = (C == 64) ? 3 : 2;
    int tot = (1 + nbuf) * 128 * row * 2;
    int mg = 128 * 64 * 8;
    return tot > mg ? tot : mg;
}

// == fused: exact fixup + edge epilogue + F/Xb(+next-layer Xc/SQ) writes ===
__global__ void fix_epi_k(const float* __restrict__ X, int ldx, int C,
                          const float* __restrict__ sq,
                          const int* __restrict__ cand,
                          const float* __restrict__ Z,
                          float* __restrict__ Fo, int O,
                          __nv_bfloat16* __restrict__ Xb, int fcol0,
                          __nv_bfloat16* __restrict__ XcOut,
                          float* __restrict__ sqOut)
{
    __shared__ int sid[4];
    __shared__ float wred[8];
    const int b = blockIdx.y, n = blockIdx.x;
    const size_t rb = (size_t)b * N_;
    const size_t w = rb + n;
    const int t = threadIdx.x, lane = t & 31;

    if (t < 32) {
        int id = 0; float d = -3.4e38f;
        if (lane < 8) {
            id = cand[w * 8 + lane];
            const float* qp = X + w * (size_t)ldx;
            const float* kp = X + (rb + id) * (size_t)ldx;
            float dot = 0.f;
            for (int c = 0; c < C; c += 4) {
                float4 a = *(const float4*)(qp + c);
                float4 b2 = *(const float4*)(kp + c);
                dot += a.x * b2.x + a.y * b2.y + a.z * b2.z + a.w * b2.w;
            }
            d = 2.0f * dot - sq[w] - sq[rb + id];
        }
        float v4[4]; int i4[4];
        #pragma unroll
        for (int r = 0; r < 4; r++) { v4[r] = -3.4e38f; i4[r] = 0x7fffffff; }
        #pragma unroll
        for (int j = 0; j < 8; j++) {
            float dj = __shfl_sync(0xffffffffu, d, j);
            int   ij = __shfl_sync(0xffffffffu, id, j);
            top4_insert(dj, ij, v4, i4);
        }
        if (lane == 0) { sid[0] = i4[0]; sid[1] = i4[1]; sid[2] = i4[2]; sid[3] = i4[3]; }
    }
    __syncthreads();
    int4 id = *(int4*)sid;
    const size_t wz = (size_t)(2 * O);
    const float* zb = Z + rb * wz;
    const float* z0 = zb + (size_t)id.x * wz;
    const float* z1 = zb + (size_t)id.y * wz;
    const float* z2 = zb + (size_t)id.z * wz;
    const float* z3 = zb + (size_t)id.w * wz;
    const float* zc = zb + (size_t)n * wz + O;
    float* fo = Fo + w * LDF;
    __nv_bfloat16* xb = Xb + w * 1024 + fcol0;
    float ss = 0.f;
    for (int o = t; o < O; o += blockDim.x) {
        float m = fmaxf(fmaxf(z0[o], z1[o]), fmaxf(z2[o], z3[o]));
        float v = fmaxf(m + zc[o], 0.f);
        fo[o] = v;
        float h = __bfloat162float(__float2bfloat16(v));
        float l = v - h;
        xb[o]       = __float2bfloat16(h);
        xb[512 + o] = __float2bfloat16(l);
        if (XcOut) {
            __nv_bfloat16* xc = XcOut + w * wz;
            xc[o]     = __float2bfloat16(h);
            xc[O + o] = __float2bfloat16(l);
        }
        ss += v * v;
    }
    if (sqOut) {
        #pragma unroll
        for (int off = 16; off; off >>= 1) ss += __shfl_xor_sync(0xffffffffu, ss, off);
        if (lane == 0) wred[t >> 5] = ss;
        __syncthreads();
        if (t == 0) {
            float s = 0.f;
            int nw = blockDim.x >> 5;
            for (int i = 0; i < nw; i++) s += wred[i];
            sqOut[w] = s;
        }
    }
}

// ====== HMMA bf16 NT-GEMM on COMPACT [h|l], 3-stage ring (R14 proven) =====
#define KC   64
#define KPAD 8
#define AROW (KC + KPAD)
#define GSTG (128 * AROW)
#define GSMEM (3 * GSTG * 2 * 2)

__global__ __launch_bounds__(256) void gemm_mmac(int tpt, int Cc,
    unsigned selA, unsigned selB,
    const __nv_bfloat16* __restrict__ A, int lda, size_t sA,
    const __nv_bfloat16* __restrict__ B, int ldb, size_t sB,
    float* __restrict__ D, int ldd, size_t sD)
{
    extern __shared__ __align__(16) __nv_bfloat16 gsm[];
    __nv_bfloat16* As = gsm;
    __nv_bfloat16* Bs = gsm + 3 * GSTG;
    const int bz = blockIdx.z;
    A += (size_t)bz * sA;
    B += (size_t)bz * sB;
    D += (size_t)bz * sD;
    const int i0 = blockIdx.y * 128;
    const int j0 = blockIdx.x * 128;
    const int t = threadIdx.x, wid = t >> 5, lane = t & 31;
    const int wm = wid & 1, wn = wid >> 1;
    const int gid = lane >> 2, tig = lane & 3;

    const uint32_t uA = s2u(As), uB = s2u(Bs);

    const int a_r  = wm * 64 + (lane & 15);
    const int a_c8 = (lane >> 4) * 8;
    const int b_r  = wn * 32 + ((lane >> 4) << 3) + (lane & 7);
    const int b_c8 = ((lane >> 3) & 1) * 8;

    float acc[4][4][4];
    #pragma unroll
    for (int mt = 0; mt < 4; mt++)
        #pragma unroll
        for (int nt = 0; nt < 4; nt++)
            #pragma unroll
            for (int e = 0; e < 4; e++) acc[mt][nt][e] = 0.f;

    const int nk = 3 * tpt;

    auto issue = [&](int k2) {
        if (k2 < nk) {
            int s = k2 % 3;
            int tb = k2 / tpt, ic = k2 % tpt;
            int offA = ic * 64 + (int)((selA >> tb) & 1u) * Cc;
            int offB = ic * 64 + (int)((selB >> tb) & 1u) * Cc;
            const __nv_bfloat16* Ag = A + (size_t)i0 * lda + offA;
            const __nv_bfloat16* Bg = B + (size_t)j0 * ldb + offB;
            uint32_t da = uA + 2u * (s * GSTG);
            uint32_t db = uB + 2u * (s * GSTG);
            #pragma unroll
            for (int q = 0; q < 4; q++) {
                int idx = t + q * 256;
                int r = idx >> 3, c8 = idx & 7;
                cp16(da + 2u * (r * AROW + c8 * 8), Ag + (size_t)r * lda + c8 * 8);
                cp16(db + 2u * (r * AROW + c8 * 8), Bg + (size_t)r * ldb + c8 * 8);
            }
        }
        CP_COMMIT();
    };

    issue(0); issue(1);
    for (int k = 0; k < nk; k++) {
        CP_WAIT1();
        __syncthreads();
        const int s = k % 3;
        const uint32_t uAs = uA + 2u * (s * GSTG);
        const uint32_t uBs = uB + 2u * (s * GSTG);
        #pragma unroll
        for (int ks = 0; ks < KC; ks += 16) {
            uint32_t af[4][4], bf[2][4];
            #pragma unroll
            for (int mt = 0; mt < 4; mt++)
                ldmx4(af[mt], uAs + 2u * ((a_r + mt * 16) * AROW + ks + a_c8));
            #pragma unroll
            for (int n2 = 0; n2 < 2; n2++)
                ldmx4(bf[n2], uBs + 2u * ((b_r + n2 * 16) * AROW + ks + b_c8));
            #pragma unroll
            for (int mt = 0; mt < 4; mt++)
                #pragma unroll
                for (int nt = 0; nt < 4; nt++)
                    mma16816(acc[mt][nt], af[mt],
                             bf[nt >> 1][(nt & 1) * 2], bf[nt >> 1][(nt & 1) * 2 + 1]);
        }
        issue(k + 2);
    }

    #pragma unroll
    for (int mt = 0; mt < 4; mt++) {
        int r = i0 + wm * 64 + mt * 16 + gid;
        #pragma unroll
        for (int nt = 0; nt < 4; nt++) {
            int c = j0 + wn * 32 + nt * 8 + tig * 2;
            *(float2*)&D[(size_t)r * ldd + c]       = make_float2(acc[mt][nt][0], acc[mt][nt][1]);
            *(float2*)&D[(size_t)(r + 8) * ldd + c] = make_float2(acc[mt][nt][2], acc[mt][nt][3]);
        }
    }
}

// ---------------- orchestration ----------------
extern "C" void kernel_launch(void* const* d_in, const int* in_sizes, int n_in,
                              void* d_out, int out_size)
{
    const float* x  = (const float*)d_in[0];
    const float* W1 = (const float*)d_in[1];
    const float* W2 = (const float*)d_in[2];
    const float* W3 = (const float*)d_in[3];
    const float* W4 = (const float*)d_in[4];
    const float* W5 = (const float*)d_in[5];
    float* out = (float*)d_out;

    void* p;
    cudaGetSymbolAddress(&p, g_X0);  float* X0 = (float*)p;
    cudaGetSymbolAddress(&p, g_F );  float* F  = (float*)p;
    cudaGetSymbolAddress(&p, g_Z );  float* Z  = (float*)p;
    cudaGetSymbolAddress(&p, g_SQ);  float* SQa = (float*)p;
    cudaGetSymbolAddress(&p, g_SQ2); float* SQb = (float*)p;
    cudaGetSymbolAddress(&p, g_ID);  int*   ID = (int*)p;
    cudaGetSymbolAddress(&p, g_C8);  int*   C8 = (int*)p;
    cudaGetSymbolAddress(&p, g_Xb);  __nv_bfloat16* Xb = (__nv_bfloat16*)p;
    cudaGetSymbolAddress(&p, g_Xc);  __nv_bfloat16* Xc = (__nv_bfloat16*)p;
    cudaGetSymbolAddress(&p, g_Wb);  __nv_bfloat16* Wb = (__nv_bfloat16*)p;

    cudaFuncSetAttribute(knn_mma2<64>,
        cudaFuncAttributeMaxDynamicSharedMemorySize, knn2_smem(64));
    cudaFuncSetAttribute(knn_mma2<128>,
        cudaFuncAttributeMaxDynamicSharedMemorySize, knn2_smem(128));
    cudaFuncSetAttribute(gemm_mmac,
        cudaFuncAttributeMaxDynamicSharedMemorySize, GSMEM);

    // sel bits per term (0=h,1=l): activations {h,h,l} -> 0b100,
    //                              weights     {h,l,h} -> 0b010
    const unsigned SEL_ACT = 0b100u;
    const unsigned SEL_W   = 0b010u;

    tr_x0_k<<<(B_*3*N_ + 255)/256, 256>>>(x, X0);

    // ---- layer 1: fp32 knn (C=3) + fully fused edge-conv (quad write) ----
    {
        sqnorm_k<<<(B_*N_*32)/256, 256>>>(X0, 3, 3, SQa);
        knn3_kernel<<<dim3(N_/64, B_), 256>>>(X0, SQa, ID);
        edge3_k<<<dim3(N_, B_), 64>>>(X0, W1, ID, F + 0, Xb, Xc, SQb);
    }

    // ---- layers 2-4: HMMA knn + compact HMMA z-GEMM + fused epilogue -----
    // Xc + sqIn produced by previous layer's epilogue; epilogue writes next.
    auto layer_tc = [&](const float* Xin, int C, int O, const float* W,
                        float* Fout, int fcol0, const float* sqIn,
                        __nv_bfloat16* XcOut, float* sqOut) {
        dim3 kg(N_/128, B_);
        if (C == 64)
            knn_mma2<64> <<<kg, 256, knn2_smem(64) >>>(Xc, sqIn, C8);
        else
            knn_mma2<128><<<kg, 256, knn2_smem(128)>>>(Xc, sqIn, C8);
        packsplit_k<<<(2*O*2*C + 255)/256, 256>>>(W, O, C, Wb);
        dim3 gg((2*O)/128, (B_*N_)/128, 1);
        gemm_mmac<<<gg, 256, GSMEM>>>(C/64, C, SEL_ACT, SEL_W,
                                      Xc, 2*C, (size_t)0,
                                      Wb, 2*C, (size_t)0,
                                      Z, 2*O, (size_t)0);
        fix_epi_k<<<dim3(N_, B_), O>>>(Xin, LDF, C, sqIn, C8, Z, Fout, O,
                                       Xb, fcol0, XcOut, sqOut);
    };
    layer_tc(F + 0,   64,  64,  W2, F + 64,  64,  SQb, Xc, SQa);  // x2
    layer_tc(F + 64,  64,  128, W3, F + 128, 128, SQa, Xc, SQb);  // x3
    layer_tc(F + 128, 128, 256, W4, F + 256, 256, SQb, nullptr, nullptr); // x4

    // ---- final: out = W5 · concat-features (Xb already populated) --------
    {
        const int C = 512;
        split_hl<<<(512*2*C + 255)/256, 256>>>(W5, C, C, 512, Wb);
        dim3 fg(N_/128, 512/128, B_);
        gemm_mmac<<<fg, 256, GSMEM>>>(C/64, C,
                                      SEL_W, SEL_ACT,
                                      Wb, 2*C, (size_t)0,
                                      Xb, 2*C, (size_t)N_ * 2 * C,
                                      out, N_, (size_t)512 * N_);
    }
}